// round 9
// baseline (speedup 1.0000x reference)
#include <cuda_runtime.h>

// Problem constants
#define NB 8
#define NC 256
#define NH 64
#define NW 64
#define NRED 64
#define NKK 9

// Scratch (device globals; zero-initialized at module load, pad columns are
// never written by any kernel so they stay zero across all replays).
// g_x1: padded layout, row stride 72, image col c at offset c+4.
__device__ float g_x1[NB * NC * NH * 72];       // 37.7 MB
// g_kern: padded layout, row stride 68, image col c at offset c+1.
__device__ float g_kern[NB * NKK * NH * 68];    // 1.25 MB

// ---------------------------------------------------------------------------
// Packed fp32x2 helpers (sm_103a)
// ---------------------------------------------------------------------------
__device__ __forceinline__ unsigned long long pack2(float v) {
    unsigned long long r;
    unsigned u = __float_as_uint(v);
    asm("mov.b64 %0, {%1, %1};" : "=l"(r) : "r"(u));
    return r;
}
__device__ __forceinline__ void fma2(unsigned long long& d,
                                     unsigned long long a,
                                     unsigned long long b) {
    asm("fma.rn.f32x2 %0, %1, %2, %0;" : "+l"(d) : "l"(a), "l"(b));
}
__device__ __forceinline__ float lo32(unsigned long long v) {
    return __uint_as_float((unsigned)(v & 0xffffffffu));
}
__device__ __forceinline__ float hi32(unsigned long long v) {
    return __uint_as_float((unsigned)(v >> 32));
}

// ---------------------------------------------------------------------------
// Kernel A1: dwconv_in (x -> g_x1 padded). Register + shuffle, no smem.
// Thread: 8 px of one row. Warp: 4 rows x 8 col-threads. Block: 32 rows.
// Grid (2, 256, 8) = 4096 blocks x 256 threads.
// ---------------------------------------------------------------------------
__global__ __launch_bounds__(256)
void tm_A1(const float* __restrict__ x,
           const float* __restrict__ w_in, const float* __restrict__ b_in)
{
    const int tid  = threadIdx.x;
    const int lane = tid & 31;
    const int warp = tid >> 5;
    const int rid  = lane >> 3;        // 0..3 row within warp
    const int ct   = lane & 7;         // 0..7 col-thread
    const int x0   = ct * 8;
    const int h0   = blockIdx.x * 32;
    const int c    = blockIdx.y;
    const int b    = blockIdx.z;
    const int gy   = h0 + warp * 4 + rid;

    const float* xc = x + (b * NC + c) * (NH * NW);

    float4 A[3], Bv[3];
#pragma unroll
    for (int dy = 0; dy < 3; dy++) {
        const int gy2 = gy + dy - 1;
        float4 a4 = {0.f, 0.f, 0.f, 0.f}, b4 = {0.f, 0.f, 0.f, 0.f};
        if (gy2 >= 0 && gy2 < NH) {
            a4 = *reinterpret_cast<const float4*>(&xc[gy2 * NW + x0]);
            b4 = *reinterpret_cast<const float4*>(&xc[gy2 * NW + x0 + 4]);
        }
        A[dy] = a4; Bv[dy] = b4;
    }

    float wv[9];
#pragma unroll
    for (int k = 0; k < 9; k++) wv[k] = __ldg(&w_in[c * 9 + k]);
    const float bias = __ldg(&b_in[c]);

    float o[8];
#pragma unroll
    for (int p = 0; p < 8; p++) o[p] = bias;

#pragma unroll
    for (int dy = 0; dy < 3; dy++) {
        float L = __shfl_up_sync(0xffffffffu, Bv[dy].w, 1);
        float R = __shfl_down_sync(0xffffffffu, A[dy].x, 1);
        if (ct == 0) L = 0.f;
        if (ct == 7) R = 0.f;
        const float a[10] = {L, A[dy].x, A[dy].y, A[dy].z, A[dy].w,
                             Bv[dy].x, Bv[dy].y, Bv[dy].z, Bv[dy].w, R};
#pragma unroll
        for (int dj = 0; dj < 3; dj++) {
            const float w = wv[dy * 3 + dj];
#pragma unroll
            for (int p = 0; p < 8; p++) o[p] = fmaf(w, a[p + dj], o[p]);
        }
    }

    float* dst = &g_x1[((b * NC + c) * NH + gy) * 72 + 4 + x0];
    float4 s0 = {o[0], o[1], o[2], o[3]};
    float4 s1 = {o[4], o[5], o[6], o[7]};
    *reinterpret_cast<float4*>(dst) = s0;
    *reinterpret_cast<float4*>(dst + 4) = s1;
}

// ---------------------------------------------------------------------------
// Kernel A2: reduce GEMM (64x256x32768) + relu + span (9x64) -> g_kern padded.
// 256 blocks x 256 threads. Block tile: 64j x 128px (= 2 image rows).
// Thread: 4j x 8px, f32x2 accumulators. Weights pre-duplicated as f32x2 pairs.
// ---------------------------------------------------------------------------
#define A2_SX 0                    // s_x[32c][128px] = 4096 floats
#define A2_SW2 4096                // s_w2[32c][64j pairs + pad], stride 136 = 4352
#define A2_SR 0                    // s_r[64j][128px] = 8192 (overlaps SX+SW2)
#define A2_AUX 8448
#define A2_WSP (A2_AUX + 0)        // 576
#define A2_BSP (A2_AUX + 576)     // 9 (pad 16)
#define A2_BRD (A2_AUX + 592)     // 64
#define A2_PART (A2_AUX + 656)    // 2 x 9 x 128 = 2304
#define A2_SMEM (A2_PART + 2304)  // 11408 floats = 45.6 KB

__global__ __launch_bounds__(256)
void tm_A2(const float* __restrict__ w_red, const float* __restrict__ b_red,
           const float* __restrict__ w_span, const float* __restrict__ b_span)
{
    __shared__ float sm[A2_SMEM];
    const int tid = threadIdx.x;
    const int px0 = blockIdx.x * 128;
    const int b = px0 >> 12;
    const int row0 = (px0 & 4095) >> 6;    // 2 rows per block

    // aux staging
    for (int i = tid; i < 656; i += 256) {
        if (i < 576)               sm[A2_AUX + i] = w_span[i];
        else if (i < 585)          sm[A2_AUX + i] = b_span[i - 576];
        else if (i >= 592)         sm[A2_AUX + i] = b_red[i - 592];
    }

    const int jg = tid >> 4;       // 0..15 (4 j each)
    const int pxg = tid & 15;      // 0..15 (8 px each)

    unsigned long long acc[4][4];
#pragma unroll
    for (int jj = 0; jj < 4; jj++)
#pragma unroll
        for (int q = 0; q < 4; q++) acc[jj][q] = 0ULL;

    float4 xr[4], wr[2];
    // prefetch chunk 0
    {
#pragma unroll
        for (int k = 0; k < 4; k++) {
            const int u = tid + k * 256;          // [0,1024)
            const int cA = u >> 5, rr = (u >> 4) & 1, g = u & 15;
            xr[k] = *reinterpret_cast<const float4*>(
                &g_x1[((b * NC + cA) * NH + row0 + rr) * 72 + 4 + g * 4]);
        }
#pragma unroll
        for (int k = 0; k < 2; k++) {
            const int i = tid + k * 256;          // [0,512)
            const int j = i >> 3, cq = i & 7;
            wr[k] = *reinterpret_cast<const float4*>(&w_red[j * NC + cq * 4]);
        }
    }

    for (int ch = 0; ch < 8; ch++) {
        // store staged chunk
#pragma unroll
        for (int k = 0; k < 4; k++) {
            const int u = tid + k * 256;
            const int cA = u >> 5, rr = (u >> 4) & 1, g = u & 15;
            *reinterpret_cast<float4*>(&sm[A2_SX + cA * 128 + rr * 64 + g * 4]) = xr[k];
        }
#pragma unroll
        for (int k = 0; k < 2; k++) {
            const int i = tid + k * 256;
            const int j = i >> 3, cq = i & 7;
            *reinterpret_cast<unsigned long long*>(&sm[A2_SW2 + (cq * 4 + 0) * 136 + j * 2]) = pack2(wr[k].x);
            *reinterpret_cast<unsigned long long*>(&sm[A2_SW2 + (cq * 4 + 1) * 136 + j * 2]) = pack2(wr[k].y);
            *reinterpret_cast<unsigned long long*>(&sm[A2_SW2 + (cq * 4 + 2) * 136 + j * 2]) = pack2(wr[k].z);
            *reinterpret_cast<unsigned long long*>(&sm[A2_SW2 + (cq * 4 + 3) * 136 + j * 2]) = pack2(wr[k].w);
        }
        __syncthreads();

        if (ch + 1 < 8) {
            const int c0c = (ch + 1) * 32;
#pragma unroll
            for (int k = 0; k < 4; k++) {
                const int u = tid + k * 256;
                const int cA = u >> 5, rr = (u >> 4) & 1, g = u & 15;
                xr[k] = *reinterpret_cast<const float4*>(
                    &g_x1[((b * NC + c0c + cA) * NH + row0 + rr) * 72 + 4 + g * 4]);
            }
#pragma unroll
            for (int k = 0; k < 2; k++) {
                const int i = tid + k * 256;
                const int j = i >> 3, cq = i & 7;
                wr[k] = *reinterpret_cast<const float4*>(&w_red[j * NC + c0c + cq * 4]);
            }
        }

        // compute over 32 channels of this chunk
#pragma unroll 4
        for (int cc = 0; cc < 32; cc++) {
            const float* wbp = &sm[A2_SW2 + cc * 136 + jg * 8];
            const ulonglong2 wA = *reinterpret_cast<const ulonglong2*>(wbp);
            const ulonglong2 wB = *reinterpret_cast<const ulonglong2*>(wbp + 4);
            const unsigned long long w2[4] = {wA.x, wA.y, wB.x, wB.y};
            const ulonglong2 xv0 = *reinterpret_cast<const ulonglong2*>(&sm[A2_SX + cc * 128 + pxg * 8]);
            const ulonglong2 xv1 = *reinterpret_cast<const ulonglong2*>(&sm[A2_SX + cc * 128 + pxg * 8 + 4]);
#pragma unroll
            for (int jj = 0; jj < 4; jj++) {
                fma2(acc[jj][0], w2[jj], xv0.x);
                fma2(acc[jj][1], w2[jj], xv0.y);
                fma2(acc[jj][2], w2[jj], xv1.x);
                fma2(acc[jj][3], w2[jj], xv1.y);
            }
        }
        __syncthreads();
    }

    // r = relu(acc + b_red) -> s_r (overlaps s_x/s_w2; safe after final sync)
#pragma unroll
    for (int jj = 0; jj < 4; jj++) {
        const int j = jg * 4 + jj;
        const float bj = sm[A2_BRD + j];
        float4 ra, rb;
        ra.x = fmaxf(lo32(acc[jj][0]) + bj, 0.f);
        ra.y = fmaxf(hi32(acc[jj][0]) + bj, 0.f);
        ra.z = fmaxf(lo32(acc[jj][1]) + bj, 0.f);
        ra.w = fmaxf(hi32(acc[jj][1]) + bj, 0.f);
        rb.x = fmaxf(lo32(acc[jj][2]) + bj, 0.f);
        rb.y = fmaxf(hi32(acc[jj][2]) + bj, 0.f);
        rb.z = fmaxf(lo32(acc[jj][3]) + bj, 0.f);
        rb.w = fmaxf(hi32(acc[jj][3]) + bj, 0.f);
        *reinterpret_cast<float4*>(&sm[A2_SR + j * 128 + pxg * 8]) = ra;
        *reinterpret_cast<float4*>(&sm[A2_SR + j * 128 + pxg * 8 + 4]) = rb;
    }
    __syncthreads();

    // span partials: 2 thread-halves each sum 32 j
    {
        const int px = tid & 127;
        const int half = tid >> 7;
        const int j0 = half * 32;
        float kf[NKK];
#pragma unroll
        for (int k = 0; k < NKK; k++) kf[k] = 0.f;
#pragma unroll 8
        for (int j = j0; j < j0 + 32; j++) {
            const float rv = sm[A2_SR + j * 128 + px];
#pragma unroll
            for (int k = 0; k < NKK; k++)
                kf[k] = fmaf(sm[A2_WSP + k * NRED + j], rv, kf[k]);
        }
#pragma unroll
        for (int k = 0; k < NKK; k++)
            sm[A2_PART + half * 1152 + k * 128 + px] = kf[k];
    }
    __syncthreads();

    if (tid < 128) {
        const int row = row0 + (tid >> 6);
        const int col = tid & 63;
#pragma unroll
        for (int k = 0; k < NKK; k++) {
            const float val = sm[A2_BSP + k]
                            + sm[A2_PART + k * 128 + tid]
                            + sm[A2_PART + 1152 + k * 128 + tid];
            g_kern[((b * NKK + k) * NH + row) * 68 + 1 + col] = val;
        }
    }
}

// ---------------------------------------------------------------------------
// Kernel B: fused involution + dwconv_out, channels PARALLEL in block.
// Block: 8 channels x (8h x 64w) output tile. Grid (8,32,8) = 2048 blocks.
// Padded global layouts make staging pure aligned f4 copies.
// ---------------------------------------------------------------------------
#define B_EH 10
#define B_EWP 68
#define B_ESZ (B_EH * B_EWP)      // 680
#define B_HH 12
#define B_HST 72
#define B_HSZ (B_HH * B_HST)      // 864
#define B_CPB 8

#define B_K  0                          // 9*680  = 6120
#define B_X  6120                       // 8*864  = 6912
#define B_Y  13032                      // 8*680  = 5440
#define B_WO 18472                      // 72
#define B_BO 18544                      // 8
#define B_SMEM_FLOATS 18552
#define B_SMEM_BYTES (B_SMEM_FLOATS * 4)  // 74208

__global__ __launch_bounds__(256)
void tm_B(const float* __restrict__ w_out, const float* __restrict__ b_out,
          float* __restrict__ out)
{
    extern __shared__ float sm[];
    const int tid = threadIdx.x;
    const int h0  = blockIdx.x * 8;
    const int cg0 = blockIdx.y * B_CPB;
    const int b   = blockIdx.z;

    // ---- phase 0a: kern ext tile, aligned f4 copy from padded g_kern.
    // 9 planes x 10 rows x 17 f4 = 1530 units.
    for (int i = tid; i < 1530; i += 256) {
        const int kk = i / 170;
        const int rem = i - kk * 170;
        const int r = rem / 17, g = rem - r * 17;
        const int gy = h0 - 1 + r;
        float4 v = {0.f, 0.f, 0.f, 0.f};
        if (gy >= 0 && gy < NH)
            v = *reinterpret_cast<const float4*>(&g_kern[((b * NKK + kk) * NH + gy) * 68 + g * 4]);
        *reinterpret_cast<float4*>(&sm[B_K + kk * B_ESZ + r * B_EWP + g * 4]) = v;
    }

    // ---- phase 0b: x1 halo, aligned f4 copy from padded g_x1.
    // Per channel: 12 rows x 18 f4 = 216 units, one channel per warp.
    {
        const int ccl = tid >> 5, lane = tid & 31;
        const float* xsrc = &g_x1[((long long)(b * NC + cg0 + ccl)) * NH * 72];
        float* xdst = &sm[B_X + ccl * B_HSZ];
        for (int u = lane; u < 216; u += 32) {
            const int r = u / 18, g = u - r * 18;
            const int gy = h0 - 2 + r;
            float4 v = {0.f, 0.f, 0.f, 0.f};
            if (gy >= 0 && gy < NH)
                v = *reinterpret_cast<const float4*>(&xsrc[gy * 72 + g * 4]);
            *reinterpret_cast<float4*>(&xdst[r * B_HST + g * 4]) = v;
        }
    }
    if (tid < 72) sm[B_WO + tid] = w_out[cg0 * 9 + tid];
    if (tid < B_CPB) sm[B_BO + tid] = b_out[cg0 + tid];
    __syncthreads();

    // ---- phase 1: involution on extended tile; kern in regs, loop channels ----
    if (tid < 170) {
        const int Ey = tid / 17;
        const int Ex0 = (tid - Ey * 17) * 4;
        float4 kr[9];
#pragma unroll
        for (int t = 0; t < 9; t++)
            kr[t] = *reinterpret_cast<const float4*>(&sm[B_K + t * B_ESZ + Ey * B_EWP + Ex0]);
#pragma unroll
        for (int cc = 0; cc < B_CPB; cc++) {
            float y0 = 0.f, y1 = 0.f, y2 = 0.f, y3 = 0.f;
#pragma unroll
            for (int ki = 0; ki < 3; ki++) {
                const float* xrow = &sm[B_X + cc * B_HSZ + (Ey + ki) * B_HST];
                const float4 A  = *reinterpret_cast<const float4*>(&xrow[Ex0]);     // .z,.w = cols Ex0-2,Ex0-1
                const float4 Bv = *reinterpret_cast<const float4*>(&xrow[Ex0 + 4]); // cols Ex0..Ex0+3
                const float a[6] = {A.z, A.w, Bv.x, Bv.y, Bv.z, Bv.w};
#pragma unroll
                for (int kj = 0; kj < 3; kj++) {
                    const float4 kv = kr[ki * 3 + kj];
                    y0 = fmaf(kv.x, a[kj + 0], y0);
                    y1 = fmaf(kv.y, a[kj + 1], y1);
                    y2 = fmaf(kv.z, a[kj + 2], y2);
                    y3 = fmaf(kv.w, a[kj + 3], y3);
                }
            }
            float4 st = {y0, y1, y2, y3};
            *reinterpret_cast<float4*>(&sm[B_Y + cc * B_ESZ + Ey * B_EWP + Ex0]) = st;
        }
    }
    __syncthreads();

    // ---- phase 2: dwconv_out from s_y, sliding 3-row window, 16 px/thread ----
    {
        const int cc = tid >> 5;
        const int lane = tid & 31;
        const int Oyg = lane >> 4;          // 0..1 -> ext row base Oyg*4
        const int Ox0 = (lane & 15) * 4;
        float wo[9];
#pragma unroll
        for (int k = 0; k < 9; k++) wo[k] = sm[B_WO + cc * 9 + k];
        const float bo = sm[B_BO + cc];

        const float* yb = &sm[B_Y + cc * B_ESZ];
        const int er0 = Oyg * 4;
        float4 r0a = *reinterpret_cast<const float4*>(&yb[(er0 + 0) * B_EWP + Ox0]);
        float4 r0b = *reinterpret_cast<const float4*>(&yb[(er0 + 0) * B_EWP + Ox0 + 4]);
        float4 r1a = *reinterpret_cast<const float4*>(&yb[(er0 + 1) * B_EWP + Ox0]);
        float4 r1b = *reinterpret_cast<const float4*>(&yb[(er0 + 1) * B_EWP + Ox0 + 4]);

        float* ob = &out[((long long)(b * NC + cg0 + cc)) * 4096 + (h0 + Oyg * 4) * NW + Ox0];
#pragma unroll
        for (int oy = 0; oy < 4; oy++) {
            const float4 r2a = *reinterpret_cast<const float4*>(&yb[(er0 + oy + 2) * B_EWP + Ox0]);
            const float4 r2b = *reinterpret_cast<const float4*>(&yb[(er0 + oy + 2) * B_EWP + Ox0 + 4]);
            float o0 = bo, o1 = bo, o2 = bo, o3 = bo;
            {
                const float a[8] = {r0a.x, r0a.y, r0a.z, r0a.w, r0b.x, r0b.y, r0b.z, r0b.w};
#pragma unroll
                for (int dj = 0; dj < 3; dj++) {
                    const float w = wo[dj];
                    o0 = fmaf(w, a[dj + 0], o0); o1 = fmaf(w, a[dj + 1], o1);
                    o2 = fmaf(w, a[dj + 2], o2); o3 = fmaf(w, a[dj + 3], o3);
                }
            }
            {
                const float a[8] = {r1a.x, r1a.y, r1a.z, r1a.w, r1b.x, r1b.y, r1b.z, r1b.w};
#pragma unroll
                for (int dj = 0; dj < 3; dj++) {
                    const float w = wo[3 + dj];
                    o0 = fmaf(w, a[dj + 0], o0); o1 = fmaf(w, a[dj + 1], o1);
                    o2 = fmaf(w, a[dj + 2], o2); o3 = fmaf(w, a[dj + 3], o3);
                }
            }
            {
                const float a[8] = {r2a.x, r2a.y, r2a.z, r2a.w, r2b.x, r2b.y, r2b.z, r2b.w};
#pragma unroll
                for (int dj = 0; dj < 3; dj++) {
                    const float w = wo[6 + dj];
                    o0 = fmaf(w, a[dj + 0], o0); o1 = fmaf(w, a[dj + 1], o1);
                    o2 = fmaf(w, a[dj + 2], o2); o3 = fmaf(w, a[dj + 3], o3);
                }
            }
            float4 st = {o0, o1, o2, o3};
            *reinterpret_cast<float4*>(&ob[oy * NW]) = st;
            r0a = r1a; r0b = r1b; r1a = r2a; r1b = r2b;
        }
    }
}

// ---------------------------------------------------------------------------
extern "C" void kernel_launch(void* const* d_in, const int* in_sizes, int n_in,
                              void* d_out, int out_size)
{
    (void)in_sizes; (void)n_in; (void)out_size;
    const float* x      = (const float*)d_in[0];
    const float* w_in   = (const float*)d_in[1];
    const float* b_in   = (const float*)d_in[2];
    const float* w_red  = (const float*)d_in[3];
    const float* b_red  = (const float*)d_in[4];
    const float* w_span = (const float*)d_in[5];
    const float* b_span = (const float*)d_in[6];
    const float* w_out  = (const float*)d_in[7];
    const float* b_out  = (const float*)d_in[8];
    float* out = (float*)d_out;

    cudaFuncSetAttribute(tm_B, cudaFuncAttributeMaxDynamicSharedMemorySize,
                         B_SMEM_BYTES);

    tm_A1<<<dim3(2, 256, 8), 256>>>(x, w_in, b_in);
    tm_A2<<<256, 256>>>(w_red, b_red, w_span, b_span);
    tm_B<<<dim3(8, 32, 8), 256, B_SMEM_BYTES>>>(w_out, b_out, out);
}

// round 12
// speedup vs baseline: 1.2896x; 1.2896x over previous
#include <cuda_runtime.h>

// Problem constants
#define NB 8
#define NC 256
#define NH 64
#define NW 64
#define NRED 64
#define NKK 9

// Scratch (device globals: allocation-free rule). Unpadded layouts.
__device__ float g_x1[NB * NC * NH * NW];     // 32 MB: output of dwconv_in
__device__ float g_kern[NB * NKK * NH * NW];  // 1.125 MB: per-pixel 3x3 kernels

// ---------------------------------------------------------------------------
// Packed fp32x2 helpers (sm_103a)
// ---------------------------------------------------------------------------
__device__ __forceinline__ unsigned long long pack2(float v) {
    unsigned long long r;
    unsigned u = __float_as_uint(v);
    asm("mov.b64 %0, {%1, %1};" : "=l"(r) : "r"(u));
    return r;
}
__device__ __forceinline__ void fma2(unsigned long long& d,
                                     unsigned long long a,
                                     unsigned long long b) {
    asm("fma.rn.f32x2 %0, %1, %2, %0;" : "+l"(d) : "l"(a), "l"(b));
}
__device__ __forceinline__ float lo32(unsigned long long v) {
    return __uint_as_float((unsigned)(v & 0xffffffffu));
}
__device__ __forceinline__ float hi32(unsigned long long v) {
    return __uint_as_float((unsigned)(v >> 32));
}

// ---------------------------------------------------------------------------
// Kernel A1: dwconv_in (x -> g_x1). Register + shuffle, no smem, no barrier.
// Thread: 8 px of one row. Warp: 4 rows x 8 col-threads. Block: 32 rows.
// Grid (2, 256, 8) = 4096 blocks x 256 threads.
// ---------------------------------------------------------------------------
__global__ __launch_bounds__(256)
void tm_A1(const float* __restrict__ x,
           const float* __restrict__ w_in, const float* __restrict__ b_in)
{
    const int tid  = threadIdx.x;
    const int lane = tid & 31;
    const int warp = tid >> 5;
    const int rid  = lane >> 3;        // 0..3 row within warp
    const int ct   = lane & 7;         // 0..7 col-thread
    const int x0   = ct * 8;
    const int h0   = blockIdx.x * 32;
    const int c    = blockIdx.y;
    const int b    = blockIdx.z;
    const int gy   = h0 + warp * 4 + rid;

    const float* xc = x + (b * NC + c) * (NH * NW);

    float4 A[3], Bv[3];
#pragma unroll
    for (int dy = 0; dy < 3; dy++) {
        const int gy2 = gy + dy - 1;
        float4 a4 = {0.f, 0.f, 0.f, 0.f}, b4 = {0.f, 0.f, 0.f, 0.f};
        if (gy2 >= 0 && gy2 < NH) {
            a4 = *reinterpret_cast<const float4*>(&xc[gy2 * NW + x0]);
            b4 = *reinterpret_cast<const float4*>(&xc[gy2 * NW + x0 + 4]);
        }
        A[dy] = a4; Bv[dy] = b4;
    }

    float wv[9];
#pragma unroll
    for (int k = 0; k < 9; k++) wv[k] = __ldg(&w_in[c * 9 + k]);
    const float bias = __ldg(&b_in[c]);

    float o[8];
#pragma unroll
    for (int p = 0; p < 8; p++) o[p] = bias;

#pragma unroll
    for (int dy = 0; dy < 3; dy++) {
        float L = __shfl_up_sync(0xffffffffu, Bv[dy].w, 1);
        float R = __shfl_down_sync(0xffffffffu, A[dy].x, 1);
        if (ct == 0) L = 0.f;
        if (ct == 7) R = 0.f;
        const float a[10] = {L, A[dy].x, A[dy].y, A[dy].z, A[dy].w,
                             Bv[dy].x, Bv[dy].y, Bv[dy].z, Bv[dy].w, R};
#pragma unroll
        for (int dj = 0; dj < 3; dj++) {
            const float w = wv[dy * 3 + dj];
#pragma unroll
            for (int p = 0; p < 8; p++) o[p] = fmaf(w, a[p + dj], o[p]);
        }
    }

    float* dst = &g_x1[((b * NC + c) * NH + gy) * NW + x0];
    float4 s0 = {o[0], o[1], o[2], o[3]};
    float4 s1 = {o[4], o[5], o[6], o[7]};
    *reinterpret_cast<float4*>(dst) = s0;
    *reinterpret_cast<float4*>(dst + 4) = s1;
}

// ---------------------------------------------------------------------------
// Kernel A2: reduce GEMM (64x256x32768) + relu + span (9x64) -> g_kern.
// 256 blocks x 128 threads. Block tile: 64j x 128px, c chunked by 32.
// Thread: 8j x 8px (px = {pxg*4..+3} U {64+pxg*4..+3} -> conflict-free LDS).
// Weights pre-duplicated as f32x2 pairs in smem.
// ---------------------------------------------------------------------------
#define A2_SX 0                   // s_x[32c][128px] = 4096 floats
#define A2_SW2 4096               // s_w2[32c][64j*2 + pad] stride 136 = 4352
#define A2_SR 0                   // s_r[64j][128px] = 8192 (overlaps SX+SW2)
#define A2_AUX 8448
#define A2_WSP (A2_AUX + 0)       // 576
#define A2_BSP (A2_AUX + 576)     // 9 (pad to 16)
#define A2_BRD (A2_AUX + 592)     // 64
#define A2_SMEM (A2_AUX + 656)    // 9104 floats = 36.4KB

__global__ __launch_bounds__(128)
void tm_A2(const float* __restrict__ w_red, const float* __restrict__ b_red,
           const float* __restrict__ w_span, const float* __restrict__ b_span)
{
    __shared__ float sm[A2_SMEM];
    const int tid = threadIdx.x;
    const int px0 = blockIdx.x * 128;
    const int b = px0 >> 12;
    const int pxin = px0 & 4095;

    // aux staging
    for (int i = tid; i < 656; i += 128) {
        if (i < 576)               sm[A2_AUX + i] = w_span[i];
        else if (i < 585)          sm[A2_AUX + i] = b_span[i - 576];
        else if (i >= 592)         sm[A2_AUX + i] = b_red[i - 592];
    }

    const int jg = tid >> 4;      // 0..7  (8 j per group)
    const int pxg = tid & 15;     // 0..15

    unsigned long long acc[8][4];
#pragma unroll
    for (int jj = 0; jj < 8; jj++)
#pragma unroll
        for (int q = 0; q < 4; q++) acc[jj][q] = 0ULL;

    const float* x1base = g_x1 + (long long)b * NC * 4096 + pxin;

    float4 xr[8], wr[4];
    // prefetch chunk 0
    {
#pragma unroll
        for (int k = 0; k < 8; k++) {
            int i = tid + k * 128;
            int cl = i >> 5, pq = i & 31;
            xr[k] = *reinterpret_cast<const float4*>(&x1base[cl * 4096 + pq * 4]);
        }
#pragma unroll
        for (int k = 0; k < 4; k++) {
            int i = tid + k * 128;
            int j = i >> 3, cq = i & 7;
            wr[k] = *reinterpret_cast<const float4*>(&w_red[j * NC + cq * 4]);
        }
    }

    for (int ch = 0; ch < 8; ch++) {
        // store staged chunk
#pragma unroll
        for (int k = 0; k < 8; k++) {
            int i = tid + k * 128;
            int cl = i >> 5, pq = i & 31;
            *reinterpret_cast<float4*>(&sm[A2_SX + cl * 128 + pq * 4]) = xr[k];
        }
#pragma unroll
        for (int k = 0; k < 4; k++) {
            int i = tid + k * 128;
            int j = i >> 3, cq = i & 7;
            *reinterpret_cast<unsigned long long*>(&sm[A2_SW2 + (cq * 4 + 0) * 136 + j * 2]) = pack2(wr[k].x);
            *reinterpret_cast<unsigned long long*>(&sm[A2_SW2 + (cq * 4 + 1) * 136 + j * 2]) = pack2(wr[k].y);
            *reinterpret_cast<unsigned long long*>(&sm[A2_SW2 + (cq * 4 + 2) * 136 + j * 2]) = pack2(wr[k].z);
            *reinterpret_cast<unsigned long long*>(&sm[A2_SW2 + (cq * 4 + 3) * 136 + j * 2]) = pack2(wr[k].w);
        }
        __syncthreads();

        if (ch + 1 < 8) {
            const int c0c = (ch + 1) * 32;
#pragma unroll
            for (int k = 0; k < 8; k++) {
                int i = tid + k * 128;
                int cl = i >> 5, pq = i & 31;
                xr[k] = *reinterpret_cast<const float4*>(&x1base[(c0c + cl) * 4096 + pq * 4]);
            }
#pragma unroll
            for (int k = 0; k < 4; k++) {
                int i = tid + k * 128;
                int j = i >> 3, cq = i & 7;
                wr[k] = *reinterpret_cast<const float4*>(&w_red[j * NC + c0c + cq * 4]);
            }
        }

        // compute over 32 channels of this chunk.
        // x loads: 16 lanes x contiguous 16B = conflict-free (half-warp dup).
#pragma unroll 4
        for (int cc = 0; cc < 32; cc++) {
            const float* wbp = &sm[A2_SW2 + cc * 136 + jg * 16];
            const ulonglong2 w01 = *reinterpret_cast<const ulonglong2*>(wbp);
            const ulonglong2 w23 = *reinterpret_cast<const ulonglong2*>(wbp + 4);
            const ulonglong2 w45 = *reinterpret_cast<const ulonglong2*>(wbp + 8);
            const ulonglong2 w67 = *reinterpret_cast<const ulonglong2*>(wbp + 12);
            const unsigned long long w2[8] = {w01.x, w01.y, w23.x, w23.y,
                                              w45.x, w45.y, w67.x, w67.y};
            const ulonglong2 xv0 = *reinterpret_cast<const ulonglong2*>(&sm[A2_SX + cc * 128 + pxg * 4]);
            const ulonglong2 xv1 = *reinterpret_cast<const ulonglong2*>(&sm[A2_SX + cc * 128 + 64 + pxg * 4]);
#pragma unroll
            for (int jj = 0; jj < 8; jj++) {
                fma2(acc[jj][0], w2[jj], xv0.x);
                fma2(acc[jj][1], w2[jj], xv0.y);
                fma2(acc[jj][2], w2[jj], xv1.x);
                fma2(acc[jj][3], w2[jj], xv1.y);
            }
        }
        __syncthreads();
    }

    // r = relu(acc + b_red) -> s_r (overlaps s_x/s_w2; safe after final sync)
#pragma unroll
    for (int jj = 0; jj < 8; jj++) {
        const int j = jg * 8 + jj;
        const float bj = sm[A2_BRD + j];
        float4 ra, rb;
        ra.x = fmaxf(lo32(acc[jj][0]) + bj, 0.f);
        ra.y = fmaxf(hi32(acc[jj][0]) + bj, 0.f);
        ra.z = fmaxf(lo32(acc[jj][1]) + bj, 0.f);
        ra.w = fmaxf(hi32(acc[jj][1]) + bj, 0.f);
        rb.x = fmaxf(lo32(acc[jj][2]) + bj, 0.f);
        rb.y = fmaxf(hi32(acc[jj][2]) + bj, 0.f);
        rb.z = fmaxf(lo32(acc[jj][3]) + bj, 0.f);
        rb.w = fmaxf(hi32(acc[jj][3]) + bj, 0.f);
        *reinterpret_cast<float4*>(&sm[A2_SR + j * 128 + pxg * 4]) = ra;
        *reinterpret_cast<float4*>(&sm[A2_SR + j * 128 + 64 + pxg * 4]) = rb;
    }
    __syncthreads();

    // span: kern[k][px] = b_span[k] + sum_j w_span[k][j] * r[j][px]
    {
        float kf[NKK];
#pragma unroll
        for (int k = 0; k < NKK; k++) kf[k] = sm[A2_BSP + k];
#pragma unroll 8
        for (int j = 0; j < NRED; j++) {
            const float rv = sm[A2_SR + j * 128 + tid];
#pragma unroll
            for (int k = 0; k < NKK; k++)
                kf[k] = fmaf(sm[A2_WSP + k * NRED + j], rv, kf[k]);
        }
#pragma unroll
        for (int k = 0; k < NKK; k++)
            g_kern[(b * NKK + k) * 4096 + pxin + tid] = kf[k];
    }
}

// ---------------------------------------------------------------------------
// Kernel B: fused involution + dwconv_out, channels PARALLEL in block.
// Block: 8 channels x (8h x 64w) output tile. Grid (8,32,8) = 2048 blocks.
// x1 halo uses aligned layout (col c at offset c+4, stride 72); kern staged
// via aligned LDG.128 + scalar STS into the ext layout.
// ---------------------------------------------------------------------------
#define B_EH 10
#define B_EWP 68
#define B_ESZ (B_EH * B_EWP)      // 680
#define B_HH 12
#define B_HST 72
#define B_HSZ (B_HH * B_HST)      // 864
#define B_CPB 8

#define B_K  0                          // 9*680  = 6120
#define B_X  6120                       // 8*864  = 6912
#define B_Y  13032                      // 8*680  = 5440
#define B_WO 18472                      // 72
#define B_BO 18544                      // 8
#define B_SMEM_FLOATS 18552
#define B_SMEM_BYTES (B_SMEM_FLOATS * 4)  // 74208

__global__ __launch_bounds__(256)
void tm_B(const float* __restrict__ w_out, const float* __restrict__ b_out,
          float* __restrict__ out)
{
    extern __shared__ float sm[];
    const int tid = threadIdx.x;
    const int h0  = blockIdx.x * 8;
    const int cg0 = blockIdx.y * B_CPB;
    const int b   = blockIdx.z;

    // ---- phase 0a: kern ext tile. aligned LDG.128, scalar STS at +1 shift.
    // 9 planes x 10 rows x 16 f4 groups = 1440 units.
    for (int i = tid; i < 1440; i += 256) {
        const int kk = i / 160;
        const int rem = i - kk * 160;
        const int r = rem >> 4, g = rem & 15;
        const int gy = h0 - 1 + r;
        float4 v = {0.f, 0.f, 0.f, 0.f};
        if (gy >= 0 && gy < NH)
            v = *reinterpret_cast<const float4*>(&g_kern[(b * NKK + kk) * 4096 + gy * NW + g * 4]);
        float* dst = &sm[B_K + kk * B_ESZ + r * B_EWP + g * 4 + 1];
        dst[0] = v.x; dst[1] = v.y; dst[2] = v.z; dst[3] = v.w;
    }
    // ext col 0 (image col -1) and ext cols 65..67: zero. 9*10 = 90 rows.
    if (tid < 90) {
        const int kk = tid / 10, r = tid - kk * 10;
        float* rowp = &sm[B_K + kk * B_ESZ + r * B_EWP];
        rowp[0] = 0.f; rowp[65] = 0.f; rowp[66] = 0.f; rowp[67] = 0.f;
    }

    // ---- phase 0b: x1 halo, aligned f4, shift-only indexing ----
    {
        const int ccl = tid >> 5, lane = tid & 31;
        const float* xsrc = &g_x1[((long long)(b * NC + cg0 + ccl)) * 4096];
        float* xdst = &sm[B_X + ccl * B_HSZ];
#pragma unroll
        for (int k = 0; k < 6; k++) {
            const int u = lane + 32 * k;     // 0..191: 12 rows x 16 f4
            const int r = u >> 4, g = u & 15;
            const int gy = h0 - 2 + r;
            float4 v = {0.f, 0.f, 0.f, 0.f};
            if (gy >= 0 && gy < NH)
                v = *reinterpret_cast<const float4*>(&xsrc[gy * NW + g * 4]);
            *reinterpret_cast<float4*>(&xdst[r * B_HST + 4 + g * 4]) = v;
        }
    }
    // edge cols (-2,-1,64,65) always outside image -> zero. 8cc x 12 rows.
    if (tid < 96) {
        const int cc2 = tid / 12, r = tid - cc2 * 12;
        float* p = &sm[B_X + cc2 * B_HSZ + r * B_HST];
        p[2] = 0.f; p[3] = 0.f; p[68] = 0.f; p[69] = 0.f;
    }
    if (tid < 72) sm[B_WO + tid] = w_out[cg0 * 9 + tid];
    if (tid < B_CPB) sm[B_BO + tid] = b_out[cg0 + tid];
    __syncthreads();

    // ---- phase 1: involution on extended tile; kern in regs, loop channels ----
    if (tid < 170) {
        const int Ey = tid / 17;
        const int Ex0 = (tid - Ey * 17) * 4;
        float4 kr[9];
#pragma unroll
        for (int t = 0; t < 9; t++)
            kr[t] = *reinterpret_cast<const float4*>(&sm[B_K + t * B_ESZ + Ey * B_EWP + Ex0]);
#pragma unroll
        for (int cc = 0; cc < B_CPB; cc++) {
            float y0 = 0.f, y1 = 0.f, y2 = 0.f, y3 = 0.f;
#pragma unroll
            for (int ki = 0; ki < 3; ki++) {
                const float* xrow = &sm[B_X + cc * B_HSZ + (Ey + ki) * B_HST];
                const float4 A  = *reinterpret_cast<const float4*>(&xrow[Ex0]);     // .z,.w = cols Ex0-2,Ex0-1
                const float4 Bv = *reinterpret_cast<const float4*>(&xrow[Ex0 + 4]); // cols Ex0..Ex0+3
                const float a[6] = {A.z, A.w, Bv.x, Bv.y, Bv.z, Bv.w};
#pragma unroll
                for (int kj = 0; kj < 3; kj++) {
                    const float4 kv = kr[ki * 3 + kj];
                    y0 = fmaf(kv.x, a[kj + 0], y0);
                    y1 = fmaf(kv.y, a[kj + 1], y1);
                    y2 = fmaf(kv.z, a[kj + 2], y2);
                    y3 = fmaf(kv.w, a[kj + 3], y3);
                }
            }
            float4 st = {y0, y1, y2, y3};
            *reinterpret_cast<float4*>(&sm[B_Y + cc * B_ESZ + Ey * B_EWP + Ex0]) = st;
        }
    }
    __syncthreads();

    // ---- phase 2: dwconv_out from s_y, sliding 3-row window, 16 px/thread ----
    {
        const int cc = tid >> 5;
        const int lane = tid & 31;
        const int Oyg = lane >> 4;          // 0..1 -> ext row base Oyg*4
        const int Ox0 = (lane & 15) * 4;
        float wo[9];
#pragma unroll
        for (int k = 0; k < 9; k++) wo[k] = sm[B_WO + cc * 9 + k];
        const float bo = sm[B_BO + cc];

        const float* yb = &sm[B_Y + cc * B_ESZ];
        const int er0 = Oyg * 4;
        float4 r0a = *reinterpret_cast<const float4*>(&yb[(er0 + 0) * B_EWP + Ox0]);
        float4 r0b = *reinterpret_cast<const float4*>(&yb[(er0 + 0) * B_EWP + Ox0 + 4]);
        float4 r1a = *reinterpret_cast<const float4*>(&yb[(er0 + 1) * B_EWP + Ox0]);
        float4 r1b = *reinterpret_cast<const float4*>(&yb[(er0 + 1) * B_EWP + Ox0 + 4]);

        float* ob = &out[((long long)(b * NC + cg0 + cc)) * 4096 + (h0 + Oyg * 4) * NW + Ox0];
#pragma unroll
        for (int oy = 0; oy < 4; oy++) {
            const float4 r2a = *reinterpret_cast<const float4*>(&yb[(er0 + oy + 2) * B_EWP + Ox0]);
            const float4 r2b = *reinterpret_cast<const float4*>(&yb[(er0 + oy + 2) * B_EWP + Ox0 + 4]);
            float o0 = bo, o1 = bo, o2 = bo, o3 = bo;
            {
                const float a[8] = {r0a.x, r0a.y, r0a.z, r0a.w, r0b.x, r0b.y, r0b.z, r0b.w};
#pragma unroll
                for (int dj = 0; dj < 3; dj++) {
                    const float w = wo[dj];
                    o0 = fmaf(w, a[dj + 0], o0); o1 = fmaf(w, a[dj + 1], o1);
                    o2 = fmaf(w, a[dj + 2], o2); o3 = fmaf(w, a[dj + 3], o3);
                }
            }
            {
                const float a[8] = {r1a.x, r1a.y, r1a.z, r1a.w, r1b.x, r1b.y, r1b.z, r1b.w};
#pragma unroll
                for (int dj = 0; dj < 3; dj++) {
                    const float w = wo[3 + dj];
                    o0 = fmaf(w, a[dj + 0], o0); o1 = fmaf(w, a[dj + 1], o1);
                    o2 = fmaf(w, a[dj + 2], o2); o3 = fmaf(w, a[dj + 3], o3);
                }
            }
            {
                const float a[8] = {r2a.x, r2a.y, r2a.z, r2a.w, r2b.x, r2b.y, r2b.z, r2b.w};
#pragma unroll
                for (int dj = 0; dj < 3; dj++) {
                    const float w = wo[6 + dj];
                    o0 = fmaf(w, a[dj + 0], o0); o1 = fmaf(w, a[dj + 1], o1);
                    o2 = fmaf(w, a[dj + 2], o2); o3 = fmaf(w, a[dj + 3], o3);
                }
            }
            float4 st = {o0, o1, o2, o3};
            *reinterpret_cast<float4*>(&ob[oy * NW]) = st;
            r0a = r1a; r0b = r1b; r1a = r2a; r1b = r2b;
        }
    }
}

// ---------------------------------------------------------------------------
extern "C" void kernel_launch(void* const* d_in, const int* in_sizes, int n_in,
                              void* d_out, int out_size)
{
    (void)in_sizes; (void)n_in; (void)out_size;
    const float* x      = (const float*)d_in[0];
    const float* w_in   = (const float*)d_in[1];
    const float* b_in   = (const float*)d_in[2];
    const float* w_red  = (const float*)d_in[3];
    const float* b_red  = (const float*)d_in[4];
    const float* w_span = (const float*)d_in[5];
    const float* b_span = (const float*)d_in[6];
    const float* w_out  = (const float*)d_in[7];
    const float* b_out  = (const float*)d_in[8];
    float* out = (float*)d_out;

    cudaFuncSetAttribute(tm_B, cudaFuncAttributeMaxDynamicSharedMemorySize,
                         B_SMEM_BYTES);

    tm_A1<<<dim3(2, 256, 8), 256>>>(x, w_in, b_in);
    tm_A2<<<256, 128>>>(w_red, b_red, w_span, b_span);
    tm_B<<<dim3(8, 32, 8), 256, B_SMEM_BYTES>>>(w_out, b_out, out);
}